// round 5
// baseline (speedup 1.0000x reference)
#include <cuda_runtime.h>

#define N_PTS 100000
#define N_PAD 100096            // multiple of 256
#define CIN   256
#define CMID  64
#define COUT  256
#define KNB   27
#define LN_EPS 1e-6f

typedef unsigned long long u64;

__device__ float g_h [N_PAD * CMID];
__device__ float g_h2[N_PAD * CMID];

#define HS_STRIDE 68
#define SMEM_AB ((2*256*HS_STRIDE + 2*64*64) * 4)   // 172032 B
#define SMEM_C  ((128*HS_STRIDE + 64*256) * 4)      // 100352 B

// ---- packed fp32x2 (FFMA2) helpers ----
__device__ __forceinline__ u64 pack2(float f) {
    u64 r; unsigned u = __float_as_uint(f);
    asm("mov.b64 %0, {%1, %1};" : "=l"(r) : "r"(u));
    return r;
}
__device__ __forceinline__ void ffma2(u64& d, u64 a, u64 b) {
    asm("fma.rn.f32x2 %0, %1, %2, %0;" : "+l"(d) : "l"(a), "l"(b));
}
__device__ __forceinline__ float2 unpack2(u64 v) {
    float lo, hi;
    asm("mov.b64 {%0, %1}, %2;" : "=f"(lo), "=f"(hi) : "l"(v));
    return make_float2(lo, hi);
}

// ---- cp.async helpers ----
__device__ __forceinline__ void cp16(unsigned d, const void* s) {
    asm volatile("cp.async.cg.shared.global [%0], [%1], 16;" :: "r"(d), "l"(s));
}
__device__ __forceinline__ void cp_commit() { asm volatile("cp.async.commit_group;"); }
__device__ __forceinline__ void cp_wait1()  { asm volatile("cp.async.wait_group 1;"); }
__device__ __forceinline__ void cp_wait0()  { asm volatile("cp.async.wait_group 0;"); }

// ---------------------------------------------------------------------------
// Kernel A: h = relu(LN(feats @ W1))   tile 256x64, K in 4 chunks of 64.
// 512 thr, double-buffered cp.async pipeline.
// warp: wr=w>>1 (8x32 rows), wc=w&1 (2x32 cols). lane: tr=lane>>2, tc=lane&3.
// thread: rows wr*32+tr+8m (m=0..3), cols wc*32+tc*8 (8).
// ---------------------------------------------------------------------------
__global__ void __launch_bounds__(512, 1) kA(const float* __restrict__ feats,
                                             const float* __restrict__ W1,
                                             const float* __restrict__ g1,
                                             const float* __restrict__ b1)
{
    extern __shared__ float sm[];
    float* hs = sm;                        // 2 x [256][68]
    float* ws = sm + 2 * 256 * HS_STRIDE;  // 2 x [64][64]

    const int t    = threadIdx.x;
    const int base = blockIdx.x * 256;
    const int lane = t & 31, w = t >> 5;
    const int wr = w >> 1, wc = w & 1;
    const int tr = lane >> 2, tc = lane & 3;
    const int rowb = wr * 32 + tr;
    const int d0   = wc * 32 + tc * 8;

    const unsigned hs_s = (unsigned)__cvta_generic_to_shared(hs);
    const unsigned ws_s = (unsigned)__cvta_generic_to_shared(ws);

    auto prefetch = [&](int kc, int buf) {
        const float* wsrc = W1 + kc * 64 * CMID;
        unsigned wb = ws_s + buf * (64 * 64 * 4);
#pragma unroll
        for (int i = 0; i < 2; i++) {
            int u = t + 512 * i;
            cp16(wb + u * 16, wsrc + u * 4);
        }
        unsigned hb = hs_s + buf * (256 * HS_STRIDE * 4);
#pragma unroll
        for (int i = 0; i < 8; i++) {
            int u = t + 512 * i;
            int r = u >> 4, c4 = u & 15;
            int gr = base + r; if (gr >= N_PTS) gr = N_PTS - 1;
            cp16(hb + (r * HS_STRIDE + c4 * 4) * 4, feats + gr * CIN + kc * 64 + c4 * 4);
        }
        cp_commit();
    };

    u64 acc[4][4];
#pragma unroll
    for (int m = 0; m < 4; m++)
#pragma unroll
        for (int p = 0; p < 4; p++) acc[m][p] = 0ULL;

    prefetch(0, 0);
    for (int kc = 0; kc < 4; kc++) {
        const int buf = kc & 1;
        if (kc < 3) { prefetch(kc + 1, buf ^ 1); cp_wait1(); } else cp_wait0();
        __syncthreads();
        const float* hb = hs + buf * (256 * HS_STRIDE);
        const float* wb = ws + buf * (64 * 64);
#pragma unroll 2
        for (int c = 0; c < 64; c++) {
            u64 A2[4];
#pragma unroll
            for (int m = 0; m < 4; m++) A2[m] = pack2(hb[(rowb + 8 * m) * HS_STRIDE + c]);
            ulonglong2 w0 = *(const ulonglong2*)&wb[c * 64 + d0];
            ulonglong2 w1 = *(const ulonglong2*)&wb[c * 64 + d0 + 4];
#pragma unroll
            for (int m = 0; m < 4; m++) {
                ffma2(acc[m][0], w0.x, A2[m]);
                ffma2(acc[m][1], w0.y, A2[m]);
                ffma2(acc[m][2], w1.x, A2[m]);
                ffma2(acc[m][3], w1.y, A2[m]);
            }
        }
        __syncthreads();
    }

    // LN over 64 cols (2 col-warps)
    float2* red = (float2*)ws;      // [256][2]
#pragma unroll
    for (int m = 0; m < 4; m++) {
        float s = 0.f, q = 0.f;
#pragma unroll
        for (int p = 0; p < 4; p++) {
            float2 v = unpack2(acc[m][p]);
            s += v.x + v.y; q += v.x * v.x + v.y * v.y;
        }
        s += __shfl_xor_sync(0xffffffffu, s, 1, 4);
        q += __shfl_xor_sync(0xffffffffu, q, 1, 4);
        s += __shfl_xor_sync(0xffffffffu, s, 2, 4);
        q += __shfl_xor_sync(0xffffffffu, q, 2, 4);
        if (tc == 0) red[(rowb + 8 * m) * 2 + wc] = make_float2(s, q);
    }
    __syncthreads();

    float4 ga = __ldg((const float4*)(g1 + d0)), gb = __ldg((const float4*)(g1 + d0 + 4));
    float4 ba = __ldg((const float4*)(b1 + d0)), bb = __ldg((const float4*)(b1 + d0 + 4));
    float lg[8] = {ga.x, ga.y, ga.z, ga.w, gb.x, gb.y, gb.z, gb.w};
    float lb[8] = {ba.x, ba.y, ba.z, ba.w, bb.x, bb.y, bb.z, bb.w};

#pragma unroll
    for (int m = 0; m < 4; m++) {
        int row = rowb + 8 * m;
        float2 pa = red[row * 2], pb = red[row * 2 + 1];
        float mu  = (pa.x + pb.x) * (1.f / 64.f);
        float var = (pa.y + pb.y) * (1.f / 64.f) - mu * mu;
        float inv = rsqrtf(var + LN_EPS);
        float o[8];
#pragma unroll
        for (int p = 0; p < 4; p++) {
            float2 v = unpack2(acc[m][p]);
            o[2 * p]     = fmaxf((v.x - mu) * inv * lg[2 * p]     + lb[2 * p],     0.f);
            o[2 * p + 1] = fmaxf((v.y - mu) * inv * lg[2 * p + 1] + lb[2 * p + 1], 0.f);
        }
        float* dst = g_h + (base + row) * CMID + d0;   // padded, unconditional
        *(float4*)(dst)     = make_float4(o[0], o[1], o[2], o[3]);
        *(float4*)(dst + 4) = make_float4(o[4], o[5], o[6], o[7]);
    }
}

// ---------------------------------------------------------------------------
// Kernel B: h2 = relu(LN( sum_k gather(h)[k] @ W2[k] ))  tile 256x64, 27 k-steps
// Same layout as kA; gather prefetched via cp.async double buffer.
// ---------------------------------------------------------------------------
__global__ void __launch_bounds__(512, 1) kB(const int*   __restrict__ nidx,
                                             const float* __restrict__ W2,
                                             const float* __restrict__ g2,
                                             const float* __restrict__ b2)
{
    extern __shared__ float sm[];
    float* hs = sm;                        // 2 x [256][68]
    float* ws = sm + 2 * 256 * HS_STRIDE;  // 2 x [64][64]

    const int t    = threadIdx.x;
    const int base = blockIdx.x * 256;
    const int lane = t & 31, w = t >> 5;
    const int wr = w >> 1, wc = w & 1;
    const int tr = lane >> 2, tc = lane & 3;
    const int rowb = wr * 32 + tr;
    const int d0   = wc * 32 + tc * 8;

    const unsigned hs_s = (unsigned)__cvta_generic_to_shared(hs);
    const unsigned ws_s = (unsigned)__cvta_generic_to_shared(ws);

    auto prefetch = [&](int k, int buf) {
        const float* wk = W2 + k * (CMID * CMID);
        unsigned wb = ws_s + buf * (64 * 64 * 4);
#pragma unroll
        for (int i = 0; i < 2; i++) {
            int u = t + 512 * i;
            cp16(wb + u * 16, wk + u * 4);
        }
        unsigned hb = hs_s + buf * (256 * HS_STRIDE * 4);
#pragma unroll
        for (int i = 0; i < 8; i++) {
            int u = t + 512 * i;
            int r = u >> 4, c4 = u & 15;
            int gr = base + r;
            int src = (gr < N_PTS) ? __ldg(nidx + gr * KNB + k) : 0;
            cp16(hb + (r * HS_STRIDE + c4 * 4) * 4, g_h + src * CMID + c4 * 4);
        }
        cp_commit();
    };

    u64 acc[4][4];
#pragma unroll
    for (int m = 0; m < 4; m++)
#pragma unroll
        for (int p = 0; p < 4; p++) acc[m][p] = 0ULL;

    prefetch(0, 0);
    for (int k = 0; k < KNB; k++) {
        const int buf = k & 1;
        if (k < KNB - 1) { prefetch(k + 1, buf ^ 1); cp_wait1(); } else cp_wait0();
        __syncthreads();
        const float* hb = hs + buf * (256 * HS_STRIDE);
        const float* wb = ws + buf * (64 * 64);
#pragma unroll 2
        for (int c = 0; c < 64; c++) {
            u64 A2[4];
#pragma unroll
            for (int m = 0; m < 4; m++) A2[m] = pack2(hb[(rowb + 8 * m) * HS_STRIDE + c]);
            ulonglong2 w0 = *(const ulonglong2*)&wb[c * 64 + d0];
            ulonglong2 w1 = *(const ulonglong2*)&wb[c * 64 + d0 + 4];
#pragma unroll
            for (int m = 0; m < 4; m++) {
                ffma2(acc[m][0], w0.x, A2[m]);
                ffma2(acc[m][1], w0.y, A2[m]);
                ffma2(acc[m][2], w1.x, A2[m]);
                ffma2(acc[m][3], w1.y, A2[m]);
            }
        }
        __syncthreads();
    }

    float2* red = (float2*)ws;
#pragma unroll
    for (int m = 0; m < 4; m++) {
        float s = 0.f, q = 0.f;
#pragma unroll
        for (int p = 0; p < 4; p++) {
            float2 v = unpack2(acc[m][p]);
            s += v.x + v.y; q += v.x * v.x + v.y * v.y;
        }
        s += __shfl_xor_sync(0xffffffffu, s, 1, 4);
        q += __shfl_xor_sync(0xffffffffu, q, 1, 4);
        s += __shfl_xor_sync(0xffffffffu, s, 2, 4);
        q += __shfl_xor_sync(0xffffffffu, q, 2, 4);
        if (tc == 0) red[(rowb + 8 * m) * 2 + wc] = make_float2(s, q);
    }
    __syncthreads();

    float4 ga = __ldg((const float4*)(g2 + d0)), gb = __ldg((const float4*)(g2 + d0 + 4));
    float4 ba = __ldg((const float4*)(b2 + d0)), bb = __ldg((const float4*)(b2 + d0 + 4));
    float lg[8] = {ga.x, ga.y, ga.z, ga.w, gb.x, gb.y, gb.z, gb.w};
    float lb[8] = {ba.x, ba.y, ba.z, ba.w, bb.x, bb.y, bb.z, bb.w};

#pragma unroll
    for (int m = 0; m < 4; m++) {
        int row = rowb + 8 * m;
        float2 pa = red[row * 2], pb = red[row * 2 + 1];
        float mu  = (pa.x + pb.x) * (1.f / 64.f);
        float var = (pa.y + pb.y) * (1.f / 64.f) - mu * mu;
        float inv = rsqrtf(var + LN_EPS);
        float o[8];
#pragma unroll
        for (int p = 0; p < 4; p++) {
            float2 v = unpack2(acc[m][p]);
            o[2 * p]     = fmaxf((v.x - mu) * inv * lg[2 * p]     + lb[2 * p],     0.f);
            o[2 * p + 1] = fmaxf((v.y - mu) * inv * lg[2 * p + 1] + lb[2 * p + 1], 0.f);
        }
        float* dst = g_h2 + (base + row) * CMID + d0;   // padded
        *(float4*)(dst)     = make_float4(o[0], o[1], o[2], o[3]);
        *(float4*)(dst + 4) = make_float4(o[4], o[5], o[6], o[7]);
    }
}

// ---------------------------------------------------------------------------
// Kernel C: out = relu(LN(h2 @ W3) + feats)   tile 128 rows x 256 cols, K=64
// 512 thr = 16 warps: wr=w>>3 (2x64 rows), wc=w&7 (8x32 cols).
// thread: rows wr*64+tr+8m (m=0..7), cols wc*32+tc*8.
// ---------------------------------------------------------------------------
__global__ void __launch_bounds__(512, 1) kC(const float* __restrict__ feats,
                                             const float* __restrict__ W3,
                                             const float* __restrict__ g3,
                                             const float* __restrict__ b3,
                                             float* __restrict__ out)
{
    extern __shared__ float sm[];
    float* hs = sm;                   // [128][68]
    float* ws = sm + 128 * HS_STRIDE; // [64][256]

    const int t    = threadIdx.x;
    const int base = blockIdx.x * 128;
    const int lane = t & 31, w = t >> 5;
    const int wr = w >> 3, wc = w & 7;
    const int tr = lane >> 2, tc = lane & 3;
    const int rowb = wr * 64 + tr;
    const int d0   = wc * 32 + tc * 8;

    // Stage h2 tile [128][64] (padded source)
#pragma unroll
    for (int i = 0; i < 4; i++) {
        int u = t + 512 * i;
        int r = u >> 4, c4 = u & 15;
        float4 v = *(const float4*)(g_h2 + (base + r) * CMID + c4 * 4);
        *(float4*)&hs[r * HS_STRIDE + c4 * 4] = v;
    }
    // Stage W3 [64][256]
#pragma unroll
    for (int i = 0; i < 8; i++) {
        int u = t + 512 * i;
        *(float4*)&ws[u * 4] = __ldg((const float4*)(W3 + u * 4));
    }
    __syncthreads();

    u64 acc[8][4];
#pragma unroll
    for (int m = 0; m < 8; m++)
#pragma unroll
        for (int p = 0; p < 4; p++) acc[m][p] = 0ULL;

#pragma unroll 2
    for (int c = 0; c < 64; c++) {
        u64 A2[8];
#pragma unroll
        for (int m = 0; m < 8; m++) A2[m] = pack2(hs[(rowb + 8 * m) * HS_STRIDE + c]);
        ulonglong2 w0 = *(const ulonglong2*)&ws[c * 256 + d0];
        ulonglong2 w1 = *(const ulonglong2*)&ws[c * 256 + d0 + 4];
#pragma unroll
        for (int m = 0; m < 8; m++) {
            ffma2(acc[m][0], w0.x, A2[m]);
            ffma2(acc[m][1], w0.y, A2[m]);
            ffma2(acc[m][2], w1.x, A2[m]);
            ffma2(acc[m][3], w1.y, A2[m]);
        }
    }

    // LN over 256 cols (8 col-warps)
    __syncthreads();
    float2* red = (float2*)hs;      // [128][8]
#pragma unroll
    for (int m = 0; m < 8; m++) {
        float s = 0.f, q = 0.f;
#pragma unroll
        for (int p = 0; p < 4; p++) {
            float2 v = unpack2(acc[m][p]);
            s += v.x + v.y; q += v.x * v.x + v.y * v.y;
        }
        s += __shfl_xor_sync(0xffffffffu, s, 1, 4);
        q += __shfl_xor_sync(0xffffffffu, q, 1, 4);
        s += __shfl_xor_sync(0xffffffffu, s, 2, 4);
        q += __shfl_xor_sync(0xffffffffu, q, 2, 4);
        if (tc == 0) red[(rowb + 8 * m) * 8 + wc] = make_float2(s, q);
    }
    __syncthreads();

    float4 ga = __ldg((const float4*)(g3 + d0)), gb = __ldg((const float4*)(g3 + d0 + 4));
    float4 ba = __ldg((const float4*)(b3 + d0)), bb = __ldg((const float4*)(b3 + d0 + 4));
    float lg[8] = {ga.x, ga.y, ga.z, ga.w, gb.x, gb.y, gb.z, gb.w};
    float lb[8] = {ba.x, ba.y, ba.z, ba.w, bb.x, bb.y, bb.z, bb.w};

#pragma unroll
    for (int m = 0; m < 8; m++) {
        int row  = rowb + 8 * m;
        int grow = base + row;
        float S = 0.f, Q = 0.f;
#pragma unroll
        for (int cw = 0; cw < 8; cw++) {
            float2 p = red[row * 8 + cw];
            S += p.x; Q += p.y;
        }
        float mu  = S * (1.f / 256.f);
        float var = Q * (1.f / 256.f) - mu * mu;
        float inv = rsqrtf(var + LN_EPS);

        if (grow < N_PTS) {
            float4 fa = __ldg((const float4*)(feats + grow * CIN + d0));
            float4 fb = __ldg((const float4*)(feats + grow * CIN + d0 + 4));
            float res[8] = {fa.x, fa.y, fa.z, fa.w, fb.x, fb.y, fb.z, fb.w};
            float o[8];
#pragma unroll
            for (int p = 0; p < 4; p++) {
                float2 v = unpack2(acc[m][p]);
                o[2 * p]     = fmaxf((v.x - mu) * inv * lg[2 * p]     + lb[2 * p]     + res[2 * p],     0.f);
                o[2 * p + 1] = fmaxf((v.y - mu) * inv * lg[2 * p + 1] + lb[2 * p + 1] + res[2 * p + 1], 0.f);
            }
            float* dst = out + grow * COUT + d0;
            *(float4*)(dst)     = make_float4(o[0], o[1], o[2], o[3]);
            *(float4*)(dst + 4) = make_float4(o[4], o[5], o[6], o[7]);
        }
    }
}

// ---------------------------------------------------------------------------
extern "C" void kernel_launch(void* const* d_in, const int* in_sizes, int n_in,
                              void* d_out, int out_size)
{
    const float* feats = (const float*)d_in[0];
    const int*   nidx  = (const int*)  d_in[1];
    const float* W1    = (const float*)d_in[2];
    const float* g1    = (const float*)d_in[3];
    const float* b1    = (const float*)d_in[4];
    const float* W2    = (const float*)d_in[5];
    const float* g2    = (const float*)d_in[6];
    const float* b2    = (const float*)d_in[7];
    const float* W3    = (const float*)d_in[8];
    const float* g3    = (const float*)d_in[9];
    const float* b3    = (const float*)d_in[10];
    float* out = (float*)d_out;

    cudaFuncSetAttribute(kA, cudaFuncAttributeMaxDynamicSharedMemorySize, SMEM_AB);
    cudaFuncSetAttribute(kB, cudaFuncAttributeMaxDynamicSharedMemorySize, SMEM_AB);
    cudaFuncSetAttribute(kC, cudaFuncAttributeMaxDynamicSharedMemorySize, SMEM_C);

    kA<<<N_PAD / 256, 512, SMEM_AB>>>(feats, W1, g1, b1);
    kB<<<N_PAD / 256, 512, SMEM_AB>>>(nidx, W2, g2, b2);
    kC<<<N_PAD / 128, 512, SMEM_C>>>(feats, W3, g3, b3, out);
}

// round 7
// speedup vs baseline: 2.0596x; 2.0596x over previous
#include <cuda_runtime.h>
#include <cstdint>

#define N_PTS 100000
#define N_PAD 100096            // multiple of 256
#define CIN   256
#define CMID  64
#define COUT  256
#define KNB   27
#define LN_EPS 1e-6f

typedef unsigned long long u64;

__device__ float  g_h  [N_PAD * CMID];            // tf32-rounded activations
__device__ float  g_h2 [N_PAD * CMID];
__device__ float2 g_W2f[KNB * 8 * 8 * 32];        // W2 as mma B-fragments (tf32)

#define SMEM_AB ((256*65 + 64*64) * 4)            // 82944 B (kA)
#define SMEM_C  ((64*65 + 64*256) * 4)            // 82176 B (kC)
#define KB_AS   (256*68)                          // floats per A buffer
#define KB_BS   4096                              // floats per B buffer
#define SMEM_KB ((2*KB_AS + 2*KB_BS) * 4)         // 172032 B

// ---- packed fp32x2 (FFMA2) helpers ----
__device__ __forceinline__ u64 pack2(float f) {
    u64 r; unsigned u = __float_as_uint(f);
    asm("mov.b64 %0, {%1, %1};" : "=l"(r) : "r"(u));
    return r;
}
__device__ __forceinline__ void ffma2(u64& d, u64 a, u64 b) {
    asm("fma.rn.f32x2 %0, %1, %2, %0;" : "+l"(d) : "l"(a), "l"(b));
}
__device__ __forceinline__ float2 unpack2(u64 v) {
    float lo, hi;
    asm("mov.b64 {%0, %1}, %2;" : "=f"(lo), "=f"(hi) : "l"(v));
    return make_float2(lo, hi);
}

// ---- tf32 round helper ----
__device__ __forceinline__ float tf32r(float x) {
    unsigned u;
    asm("cvt.rna.tf32.f32 %0, %1;" : "=r"(u) : "f"(x));
    return __uint_as_float(u);
}

// ---- cp.async helpers ----
__device__ __forceinline__ void cp16(unsigned d, const void* s) {
    asm volatile("cp.async.cg.shared.global [%0], [%1], 16;" :: "r"(d), "l"(s));
}
__device__ __forceinline__ void cp_commit() { asm volatile("cp.async.commit_group;"); }
__device__ __forceinline__ void cp_wait1()  { asm volatile("cp.async.wait_group 1;"); }
__device__ __forceinline__ void cp_wait0()  { asm volatile("cp.async.wait_group 0;"); }

// ---- mma.sync m16n8k8 tf32 ----
__device__ __forceinline__ void mma_tf32(float* d, const unsigned* a, const unsigned* b) {
    asm volatile(
        "mma.sync.aligned.m16n8k8.row.col.f32.tf32.tf32.f32 "
        "{%0,%1,%2,%3}, {%4,%5,%6,%7}, {%8,%9}, {%0,%1,%2,%3};"
        : "+f"(d[0]), "+f"(d[1]), "+f"(d[2]), "+f"(d[3])
        : "r"(a[0]), "r"(a[1]), "r"(a[2]), "r"(a[3]), "r"(b[0]), "r"(b[1]));
}

// ---------------------------------------------------------------------------
// Prep: W2[k][c][d] -> B fragments for m16n8k8 (col-major B: k-dim=c, n=d),
// tf32-rounded. Frag (k, kc, nt): lane holds {b0 = W2[c=kc*8+(l&3)][d=nt*8+(l>>2)],
// b1 = same at c+4}. Stored as float2 at [((k*8+kc)*8+nt)*32 + lane].
// ---------------------------------------------------------------------------
__global__ void __launch_bounds__(256) kPrep(const float* __restrict__ W2)
{
    const int k = blockIdx.x, t = threadIdx.x;
    const float* src = W2 + k * 4096;
#pragma unroll
    for (int e = t; e < 2048; e += 256) {
        int lane = e & 31, nt = (e >> 5) & 7, kc = e >> 8;
        int c0 = kc * 8 + (lane & 3);
        int d  = nt * 8 + (lane >> 2);
        float v0 = tf32r(__ldg(src + c0 * 64 + d));
        float v1 = tf32r(__ldg(src + (c0 + 4) * 64 + d));
        g_W2f[(k * 64 + kc * 8 + nt) * 32 + lane] = make_float2(v0, v1);
    }
}

// ---------------------------------------------------------------------------
// Kernel A: h = relu(LN(feats @ W1)), outputs tf32-rounded. (R4 FFMA2 version)
// ---------------------------------------------------------------------------
__global__ void __launch_bounds__(256, 2) kA(const float* __restrict__ feats,
                                             const float* __restrict__ W1,
                                             const float* __restrict__ g1,
                                             const float* __restrict__ b1)
{
    extern __shared__ float sm[];
    float* fs = sm;                 // [256][65]
    float* ws = sm + 256 * 65;      // [64][64]

    const int t    = threadIdx.x;
    const int base = blockIdx.x * 256;
    const int lane = t & 31, w = t >> 5;
    const int wr = w >> 1, wc = w & 1;
    const int tr = lane >> 2, tc = lane & 3;
    const int rbase = wr * 64 + tr * 4;
    const int d0    = wc * 32 + tc * 8;

    u64 acc[8][4];
#pragma unroll
    for (int i = 0; i < 8; i++)
#pragma unroll
        for (int p = 0; p < 4; p++) acc[i][p] = 0ULL;

    for (int kc = 0; kc < 4; kc++) {
        if (kc) __syncthreads();
        const float* wsrc = W1 + kc * 64 * CMID;
#pragma unroll
        for (int i = 0; i < 4; i++) {
            int u = t + 256 * i;
            *(float4*)&ws[u * 4] = __ldg((const float4*)(wsrc + u * 4));
        }
#pragma unroll
        for (int i = 0; i < 16; i++) {
            int u = t + 256 * i;
            int r = u >> 4, c4 = u & 15;
            int gr = base + r;
            float4 v = make_float4(0.f, 0.f, 0.f, 0.f);
            if (gr < N_PTS) v = __ldg((const float4*)(feats + gr * CIN + kc * 64 + c4 * 4));
            float* p = &fs[r * 65 + c4 * 4];
            p[0] = v.x; p[1] = v.y; p[2] = v.z; p[3] = v.w;
        }
        __syncthreads();

#pragma unroll 2
        for (int c = 0; c < 64; c++) {
            u64 A2[8];
#pragma unroll
            for (int i = 0; i < 8; i++)
                A2[i] = pack2(fs[(rbase + (i & 3) + 32 * (i >> 2)) * 65 + c]);
            ulonglong2 w0 = *(const ulonglong2*)&ws[c * 64 + d0];
            ulonglong2 w1 = *(const ulonglong2*)&ws[c * 64 + d0 + 4];
#pragma unroll
            for (int i = 0; i < 8; i++) {
                ffma2(acc[i][0], w0.x, A2[i]);
                ffma2(acc[i][1], w0.y, A2[i]);
                ffma2(acc[i][2], w1.x, A2[i]);
                ffma2(acc[i][3], w1.y, A2[i]);
            }
        }
    }

    __syncthreads();
    float2* red = (float2*)ws;      // [256][2]
#pragma unroll
    for (int i = 0; i < 8; i++) {
        float s = 0.f, q = 0.f;
#pragma unroll
        for (int p = 0; p < 4; p++) {
            float2 v = unpack2(acc[i][p]);
            s += v.x + v.y; q += v.x * v.x + v.y * v.y;
        }
        s += __shfl_xor_sync(0xffffffffu, s, 1, 4);
        q += __shfl_xor_sync(0xffffffffu, q, 1, 4);
        s += __shfl_xor_sync(0xffffffffu, s, 2, 4);
        q += __shfl_xor_sync(0xffffffffu, q, 2, 4);
        if (tc == 0) red[(rbase + (i & 3) + 32 * (i >> 2)) * 2 + wc] = make_float2(s, q);
    }
    __syncthreads();

    float4 ga = __ldg((const float4*)(g1 + d0)), gb = __ldg((const float4*)(g1 + d0 + 4));
    float4 ba = __ldg((const float4*)(b1 + d0)), bb = __ldg((const float4*)(b1 + d0 + 4));
    float lg[8] = {ga.x, ga.y, ga.z, ga.w, gb.x, gb.y, gb.z, gb.w};
    float lb[8] = {ba.x, ba.y, ba.z, ba.w, bb.x, bb.y, bb.z, bb.w};

#pragma unroll
    for (int i = 0; i < 8; i++) {
        int row = rbase + (i & 3) + 32 * (i >> 2);
        float2 pa = red[row * 2], pb = red[row * 2 + 1];
        float mu  = (pa.x + pb.x) * (1.f / 64.f);
        float var = (pa.y + pb.y) * (1.f / 64.f) - mu * mu;
        float inv = rsqrtf(var + LN_EPS);
        float o[8];
#pragma unroll
        for (int p = 0; p < 4; p++) {
            float2 v = unpack2(acc[i][p]);
            o[2 * p]     = tf32r(fmaxf((v.x - mu) * inv * lg[2 * p]     + lb[2 * p],     0.f));
            o[2 * p + 1] = tf32r(fmaxf((v.y - mu) * inv * lg[2 * p + 1] + lb[2 * p + 1], 0.f));
        }
        float* dst = g_h + (base + row) * CMID + d0;
        *(float4*)(dst)     = make_float4(o[0], o[1], o[2], o[3]);
        *(float4*)(dst + 4) = make_float4(o[4], o[5], o[6], o[7]);
    }
}

// ---------------------------------------------------------------------------
// Kernel B (tensor, mma.sync tf32): h2 = relu(LN(sum_k gather(h)[k] @ W2[k]))
// Tile 256 rows, 256 thr = 8 warps; warp w: rows w*32..+31, cols 0..63.
// D = 2 m-tiles x 8 n-tiles m16n8k8 frags. A staged stride-68, B pre-fragged.
// cp.async double buffer over the 27 k-steps.
// ---------------------------------------------------------------------------
__global__ void __launch_bounds__(256, 1) kB(const int*   __restrict__ nidx,
                                             const float* __restrict__ g2v,
                                             const float* __restrict__ b2v)
{
    extern __shared__ float sm[];
    float* As = sm;                  // 2 x [256][68]
    float* Bf = sm + 2 * KB_AS;      // 2 x [4096]

    const int t    = threadIdx.x;
    const int base = blockIdx.x * 256;
    const int lane = t & 31, w = t >> 5;
    const int qr = lane >> 2, ql = lane & 3;

    const unsigned As_s = (unsigned)__cvta_generic_to_shared(As);
    const unsigned Bf_s = (unsigned)__cvta_generic_to_shared(Bf);

    auto prefetch = [&](int k, int buf) {
        // B fragments: 16KB contiguous
        const float4* bsrc = (const float4*)(g_W2f + k * 2048);
        unsigned bb = Bf_s + buf * (KB_BS * 4);
#pragma unroll
        for (int i = 0; i < 4; i++) {
            int u = t + 256 * i;
            cp16(bb + u * 16, bsrc + u);
        }
        // A gather: 256 rows x 16 float4
        unsigned ab = As_s + buf * (KB_AS * 4);
#pragma unroll
        for (int i = 0; i < 16; i++) {
            int u = t + 256 * i;
            int r = u >> 4, c4 = u & 15;
            int gr = base + r;
            int src = (gr < N_PTS) ? __ldg(nidx + gr * KNB + k) : 0;
            cp16(ab + (r * 68 + c4 * 4) * 4, g_h + src * CMID + c4 * 4);
        }
        cp_commit();
    };

    float d[2][8][4];
#pragma unroll
    for (int mt = 0; mt < 2; mt++)
#pragma unroll
        for (int nt = 0; nt < 8; nt++)
#pragma unroll
            for (int p = 0; p < 4; p++) d[mt][nt][p] = 0.f;

    prefetch(0, 0);
    for (int k = 0; k < KNB; k++) {
        const int buf = k & 1;
        if (k < KNB - 1) { prefetch(k + 1, buf ^ 1); cp_wait1(); } else cp_wait0();
        __syncthreads();

        const unsigned* Ab = (const unsigned*)(As + buf * KB_AS);
        const float2*   Bb = (const float2*)(Bf + buf * KB_BS);

#pragma unroll
        for (int kc = 0; kc < 8; kc++) {
            unsigned a[2][4];
#pragma unroll
            for (int mt = 0; mt < 2; mt++) {
                int r0 = w * 32 + mt * 16 + qr;
                int c0 = kc * 8 + ql;
                a[mt][0] = Ab[r0 * 68 + c0];
                a[mt][1] = Ab[(r0 + 8) * 68 + c0];
                a[mt][2] = Ab[r0 * 68 + c0 + 4];
                a[mt][3] = Ab[(r0 + 8) * 68 + c0 + 4];
            }
            unsigned b[8][2];
#pragma unroll
            for (int nt = 0; nt < 8; nt++) {
                float2 bv = Bb[(kc * 8 + nt) * 32 + lane];
                b[nt][0] = __float_as_uint(bv.x);
                b[nt][1] = __float_as_uint(bv.y);
            }
#pragma unroll
            for (int mt = 0; mt < 2; mt++)
#pragma unroll
                for (int nt = 0; nt < 8; nt++)
                    mma_tf32(d[mt][nt], a[mt], b[nt]);
        }
        __syncthreads();
    }

    // Epilogue: per-row LN, quad-local (width-4 shfl). Thread owns 4 rows x 16 cols.
    float2 lg[8], lb[8];
#pragma unroll
    for (int nt = 0; nt < 8; nt++) {
        lg[nt] = __ldg((const float2*)(g2v + nt * 8 + 2 * ql));
        lb[nt] = __ldg((const float2*)(b2v + nt * 8 + 2 * ql));
    }

#pragma unroll
    for (int mt = 0; mt < 2; mt++) {
#pragma unroll
        for (int h = 0; h < 2; h++) {
            int row = w * 32 + mt * 16 + qr + 8 * h;
            float s = 0.f, q = 0.f;
#pragma unroll
            for (int nt = 0; nt < 8; nt++) {
                float v0 = d[mt][nt][2 * h], v1 = d[mt][nt][2 * h + 1];
                s += v0 + v1; q += v0 * v0 + v1 * v1;
            }
            s += __shfl_xor_sync(0xffffffffu, s, 1, 4);
            q += __shfl_xor_sync(0xffffffffu, q, 1, 4);
            s += __shfl_xor_sync(0xffffffffu, s, 2, 4);
            q += __shfl_xor_sync(0xffffffffu, q, 2, 4);
            float mu  = s * (1.f / 64.f);
            float var = q * (1.f / 64.f) - mu * mu;
            float inv = rsqrtf(var + LN_EPS);

            float* dst = g_h2 + (base + row) * CMID + 2 * ql;   // padded, no guard
#pragma unroll
            for (int nt = 0; nt < 8; nt++) {
                float2 o;
                o.x = fmaxf((d[mt][nt][2 * h]     - mu) * inv * lg[nt].x + lb[nt].x, 0.f);
                o.y = fmaxf((d[mt][nt][2 * h + 1] - mu) * inv * lg[nt].y + lb[nt].y, 0.f);
                *(float2*)(dst + nt * 8) = o;
            }
        }
    }
}

// ---------------------------------------------------------------------------
// Kernel C (R4): out = relu(LN(h2 @ W3) + feats)
// ---------------------------------------------------------------------------
__global__ void __launch_bounds__(256, 2) kC(const float* __restrict__ feats,
                                             const float* __restrict__ W3,
                                             const float* __restrict__ g3,
                                             const float* __restrict__ b3,
                                             float* __restrict__ out)
{
    extern __shared__ float sm[];
    float* hs = sm;                 // [64][65]
    float* ws = sm + 64 * 65;       // [64][256]

    const int t    = threadIdx.x;
    const int base = blockIdx.x * 64;
    const int lane = t & 31, w = t >> 5;
    const int tr = lane >> 2, tc = lane & 3;
    const int rbase = tr * 4;
    const int d0    = w * 32 + tc * 8;

#pragma unroll
    for (int i = 0; i < 4; i++) {
        int u = t + 256 * i;
        int r = u >> 4, c4 = u & 15;
        float4 v = *(const float4*)(g_h2 + (base + r) * CMID + c4 * 4);
        float* p = &hs[r * 65 + c4 * 4];
        p[0] = v.x; p[1] = v.y; p[2] = v.z; p[3] = v.w;
    }
#pragma unroll
    for (int i = 0; i < 16; i++) {
        int u = t + 256 * i;
        *(float4*)&ws[u * 4] = __ldg((const float4*)(W3 + u * 4));
    }
    __syncthreads();

    u64 acc[8][4];
#pragma unroll
    for (int i = 0; i < 8; i++)
#pragma unroll
        for (int p = 0; p < 4; p++) acc[i][p] = 0ULL;

#pragma unroll 2
    for (int c = 0; c < 64; c++) {
        u64 A2[8];
#pragma unroll
        for (int i = 0; i < 8; i++)
            A2[i] = pack2(hs[(rbase + (i & 3) + 32 * (i >> 2)) * 65 + c]);
        ulonglong2 w0 = *(const ulonglong2*)&ws[c * 256 + d0];
        ulonglong2 w1 = *(const ulonglong2*)&ws[c * 256 + d0 + 4];
#pragma unroll
        for (int i = 0; i < 8; i++) {
            ffma2(acc[i][0], w0.x, A2[i]);
            ffma2(acc[i][1], w0.y, A2[i]);
            ffma2(acc[i][2], w1.x, A2[i]);
            ffma2(acc[i][3], w1.y, A2[i]);
        }
    }

    __syncthreads();
    float2* red = (float2*)hs;      // [64][8]
#pragma unroll
    for (int i = 0; i < 8; i++) {
        float s = 0.f, q = 0.f;
#pragma unroll
        for (int p = 0; p < 4; p++) {
            float2 v = unpack2(acc[i][p]);
            s += v.x + v.y; q += v.x * v.x + v.y * v.y;
        }
        s += __shfl_xor_sync(0xffffffffu, s, 1, 4);
        q += __shfl_xor_sync(0xffffffffu, q, 1, 4);
        s += __shfl_xor_sync(0xffffffffu, s, 2, 4);
        q += __shfl_xor_sync(0xffffffffu, q, 2, 4);
        if (tc == 0) red[(rbase + (i & 3) + 32 * (i >> 2)) * 8 + w] = make_float2(s, q);
    }
    __syncthreads();

    float4 ga = __ldg((const float4*)(g3 + d0)), gb = __ldg((const float4*)(g3 + d0 + 4));
    float4 ba = __ldg((const float4*)(b3 + d0)), bb = __ldg((const float4*)(b3 + d0 + 4));
    float lg[8] = {ga.x, ga.y, ga.z, ga.w, gb.x, gb.y, gb.z, gb.w};
    float lb[8] = {ba.x, ba.y, ba.z, ba.w, bb.x, bb.y, bb.z, bb.w};

#pragma unroll
    for (int i = 0; i < 8; i++) {
        int row  = rbase + (i & 3) + 32 * (i >> 2);
        int grow = base + row;
        float S = 0.f, Q = 0.f;
#pragma unroll
        for (int cw = 0; cw < 8; cw++) {
            float2 p = red[row * 8 + cw];
            S += p.x; Q += p.y;
        }
        float mu  = S * (1.f / 256.f);
        float var = Q * (1.f / 256.f) - mu * mu;
        float inv = rsqrtf(var + LN_EPS);

        if (grow < N_PTS) {
            float4 fa = __ldg((const float4*)(feats + grow * CIN + d0));
            float4 fb = __ldg((const float4*)(feats + grow * CIN + d0 + 4));
            float res[8] = {fa.x, fa.y, fa.z, fa.w, fb.x, fb.y, fb.z, fb.w};
            float o[8];
#pragma unroll
            for (int p = 0; p < 4; p++) {
                float2 v = unpack2(acc[i][p]);
                o[2 * p]     = fmaxf((v.x - mu) * inv * lg[2 * p]     + lb[2 * p]     + res[2 * p],     0.f);
                o[2 * p + 1] = fmaxf((v.y - mu) * inv * lg[2 * p + 1] + lb[2 * p + 1] + res[2 * p + 1], 0.f);
            }
            float* dst = out + grow * COUT + d0;
            *(float4*)(dst)     = make_float4(o[0], o[1], o[2], o[3]);
            *(float4*)(dst + 4) = make_float4(o[4], o[5], o[6], o[7]);
        }
    }
}

// ---------------------------------------------------------------------------
extern "C" void kernel_launch(void* const* d_in, const int* in_sizes, int n_in,
                              void* d_out, int out_size)
{
    const float* feats = (const float*)d_in[0];
    const int*   nidx  = (const int*)  d_in[1];
    const float* W1    = (const float*)d_in[2];
    const float* g1    = (const float*)d_in[3];
    const float* b1    = (const float*)d_in[4];
    const float* W2    = (const float*)d_in[5];
    const float* g2    = (const float*)d_in[6];
    const float* b2    = (const float*)d_in[7];
    const float* W3    = (const float*)d_in[8];
    const float* g3    = (const float*)d_in[9];
    const float* b3    = (const float*)d_in[10];
    float* out = (float*)d_out;

    cudaFuncSetAttribute(kA, cudaFuncAttributeMaxDynamicSharedMemorySize, SMEM_AB);
    cudaFuncSetAttribute(kB, cudaFuncAttributeMaxDynamicSharedMemorySize, SMEM_KB);
    cudaFuncSetAttribute(kC, cudaFuncAttributeMaxDynamicSharedMemorySize, SMEM_C);

    kPrep<<<KNB, 256>>>(W2);
    kA<<<N_PAD / 256, 256, SMEM_AB>>>(feats, W1, g1, b1);
    kB<<<N_PAD / 256, 256, SMEM_KB>>>(nidx, g2, b2);
    kC<<<(N_PTS + 63) / 64, 256, SMEM_C>>>(feats, W3, g3, b3, out);
}

// round 9
// speedup vs baseline: 2.7580x; 1.3391x over previous
#include <cuda_runtime.h>
#include <cstdint>

#define N_PTS 100000
#define N_PAD 100096            // multiple of 256
#define CIN   256
#define CMID  64
#define COUT  256
#define KNB   27
#define LN_EPS 1e-6f

__device__ float  g_h  [N_PAD * CMID];            // tf32-rounded activations
__device__ float  g_h2 [N_PAD * CMID];            // tf32-rounded activations
__device__ float2 g_W2f[KNB * 64 * 32];           // W2 B-fragments (tf32)
__device__ float2 g_W1f[32 * 8 * 32];             // W1 B-fragments (tf32)
__device__ float2 g_W3f[8 * 32 * 32];             // W3 B-fragments (tf32)

#define KB_AS   (256*68)                          // floats per A buffer
#define KB_BS   4096                              // floats per B buffer (16KB)
#define SMEM_AB ((2*KB_AS + 2*KB_BS) * 4)         // 172032 B (kA, kB)
#define SMEM_C  ((64*68 + 16384) * 4)             // 82944 B  (kC: A + 64KB W3 frags)

// ---- tf32 round helpers ----
__device__ __forceinline__ float tf32r(float x) {
    unsigned u;
    asm("cvt.rna.tf32.f32 %0, %1;" : "=r"(u) : "f"(x));
    return __uint_as_float(u);
}
__device__ __forceinline__ unsigned tf32b(float x) {
    unsigned u;
    asm("cvt.rna.tf32.f32 %0, %1;" : "=r"(u) : "f"(x));
    return u;
}

// ---- cp.async helpers ----
__device__ __forceinline__ void cp16(unsigned d, const void* s) {
    asm volatile("cp.async.cg.shared.global [%0], [%1], 16;" :: "r"(d), "l"(s));
}
__device__ __forceinline__ void cp_commit() { asm volatile("cp.async.commit_group;"); }
__device__ __forceinline__ void cp_wait1()  { asm volatile("cp.async.wait_group 1;"); }
__device__ __forceinline__ void cp_wait0()  { asm volatile("cp.async.wait_group 0;"); }

// ---- mma.sync m16n8k8 tf32 ----
__device__ __forceinline__ void mma_tf32(float* d, const unsigned* a, const unsigned* b) {
    asm volatile(
        "mma.sync.aligned.m16n8k8.row.col.f32.tf32.tf32.f32 "
        "{%0,%1,%2,%3}, {%4,%5,%6,%7}, {%8,%9}, {%0,%1,%2,%3};"
        : "+f"(d[0]), "+f"(d[1]), "+f"(d[2]), "+f"(d[3])
        : "r"(a[0]), "r"(a[1]), "r"(a[2]), "r"(a[3]), "r"(b[0]), "r"(b[1]));
}

// ---------------------------------------------------------------------------
// Prep: build tf32 B-fragments for all three weight matrices.
// Frag (kc, nt): lane holds {b0 = W[c=kc*8+(l&3)][n=nt*8+(l>>2)], b1 = same at c+4}.
// blocks 0..26 -> W2[k]; block 27 -> W1; block 28 -> W3.
// ---------------------------------------------------------------------------
__global__ void __launch_bounds__(256) kPrep(const float* __restrict__ W1,
                                             const float* __restrict__ W2,
                                             const float* __restrict__ W3)
{
    const int blk = blockIdx.x, t = threadIdx.x;
    if (blk < KNB) {
        const float* src = W2 + blk * 4096;
#pragma unroll
        for (int e = t; e < 2048; e += 256) {
            int lane = e & 31, nt = (e >> 5) & 7, kc = e >> 8;
            int c0 = kc * 8 + (lane & 3);
            int d  = nt * 8 + (lane >> 2);
            g_W2f[(blk * 64 + kc * 8 + nt) * 32 + lane] =
                make_float2(tf32r(__ldg(src + c0 * 64 + d)),
                            tf32r(__ldg(src + (c0 + 4) * 64 + d)));
        }
    } else if (blk == KNB) {
        // W1: [256][64], 32 kc-steps x 8 nt
        for (int e = t; e < 8192; e += 256) {
            int lane = e & 31, nt = (e >> 5) & 7, kcg = e >> 8;
            int c0 = kcg * 8 + (lane & 3);
            int d  = nt * 8 + (lane >> 2);
            g_W1f[(kcg * 8 + nt) * 32 + lane] =
                make_float2(tf32r(__ldg(W1 + c0 * 64 + d)),
                            tf32r(__ldg(W1 + (c0 + 4) * 64 + d)));
        }
    } else {
        // W3: [64][256], 8 kc-steps x 32 nt
        for (int e = t; e < 8192; e += 256) {
            int lane = e & 31, nt = (e >> 5) & 31, kc = e >> 10;
            int c0 = kc * 8 + (lane & 3);
            int d  = nt * 8 + (lane >> 2);
            g_W3f[(kc * 32 + nt) * 32 + lane] =
                make_float2(tf32r(__ldg(W3 + c0 * 256 + d)),
                            tf32r(__ldg(W3 + (c0 + 4) * 256 + d)));
        }
    }
}

// ---------------------------------------------------------------------------
// Kernel A (tensor): h = relu(LN(feats @ W1)), output tf32-rounded.
// Tile 256 rows x 64 cols, K=256 in 4 chunks of 64; cp.async double buffer.
// 8 warps; warp w: rows w*32..+31, D = 2mt x 8nt m16n8k8 frags.
// ---------------------------------------------------------------------------
__global__ void __launch_bounds__(256, 1) kA(const float* __restrict__ feats,
                                             const float* __restrict__ g1v,
                                             const float* __restrict__ b1v)
{
    extern __shared__ float sm[];
    float* As = sm;                  // 2 x [256][68]
    float* Bf = sm + 2 * KB_AS;      // 2 x [4096]

    const int t    = threadIdx.x;
    const int base = blockIdx.x * 256;
    const int lane = t & 31, w = t >> 5;
    const int qr = lane >> 2, ql = lane & 3;

    const unsigned As_s = (unsigned)__cvta_generic_to_shared(As);
    const unsigned Bf_s = (unsigned)__cvta_generic_to_shared(Bf);

    auto prefetch = [&](int ch, int buf) {
        const float4* bsrc = (const float4*)(g_W1f + ch * 2048);
        unsigned bb = Bf_s + buf * (KB_BS * 4);
#pragma unroll
        for (int i = 0; i < 4; i++) {
            int u = t + 256 * i;
            cp16(bb + u * 16, bsrc + u);
        }
        unsigned ab = As_s + buf * (KB_AS * 4);
#pragma unroll
        for (int i = 0; i < 16; i++) {
            int u = t + 256 * i;
            int r = u >> 4, c4 = u & 15;
            int gr = base + r; if (gr >= N_PTS) gr = N_PTS - 1;
            cp16(ab + (r * 68 + c4 * 4) * 4, feats + gr * CIN + ch * 64 + c4 * 4);
        }
        cp_commit();
    };

    float d[2][8][4];
#pragma unroll
    for (int mt = 0; mt < 2; mt++)
#pragma unroll
        for (int nt = 0; nt < 8; nt++)
#pragma unroll
            for (int p = 0; p < 4; p++) d[mt][nt][p] = 0.f;

    prefetch(0, 0);
    for (int ch = 0; ch < 4; ch++) {
        const int buf = ch & 1;
        if (ch < 3) { prefetch(ch + 1, buf ^ 1); cp_wait1(); } else cp_wait0();
        __syncthreads();

        const float*  Ab = As + buf * KB_AS;
        const float2* Bb = (const float2*)(Bf + buf * KB_BS);

#pragma unroll
        for (int kc = 0; kc < 8; kc++) {
            unsigned a[2][4];
#pragma unroll
            for (int mt = 0; mt < 2; mt++) {
                int r0 = w * 32 + mt * 16 + qr;
                int c0 = kc * 8 + ql;
                a[mt][0] = tf32b(Ab[r0 * 68 + c0]);
                a[mt][1] = tf32b(Ab[(r0 + 8) * 68 + c0]);
                a[mt][2] = tf32b(Ab[r0 * 68 + c0 + 4]);
                a[mt][3] = tf32b(Ab[(r0 + 8) * 68 + c0 + 4]);
            }
            unsigned b[8][2];
#pragma unroll
            for (int nt = 0; nt < 8; nt++) {
                float2 bv = Bb[(kc * 8 + nt) * 32 + lane];
                b[nt][0] = __float_as_uint(bv.x);
                b[nt][1] = __float_as_uint(bv.y);
            }
#pragma unroll
            for (int mt = 0; mt < 2; mt++)
#pragma unroll
                for (int nt = 0; nt < 8; nt++)
                    mma_tf32(d[mt][nt], a[mt], b[nt]);
        }
        __syncthreads();
    }

    float2 lg[8], lb[8];
#pragma unroll
    for (int nt = 0; nt < 8; nt++) {
        lg[nt] = __ldg((const float2*)(g1v + nt * 8 + 2 * ql));
        lb[nt] = __ldg((const float2*)(b1v + nt * 8 + 2 * ql));
    }

#pragma unroll
    for (int mt = 0; mt < 2; mt++) {
#pragma unroll
        for (int h = 0; h < 2; h++) {
            int row = w * 32 + mt * 16 + qr + 8 * h;
            float s = 0.f, q = 0.f;
#pragma unroll
            for (int nt = 0; nt < 8; nt++) {
                float v0 = d[mt][nt][2 * h], v1 = d[mt][nt][2 * h + 1];
                s += v0 + v1; q += v0 * v0 + v1 * v1;
            }
            s += __shfl_xor_sync(0xffffffffu, s, 1, 4);
            q += __shfl_xor_sync(0xffffffffu, q, 1, 4);
            s += __shfl_xor_sync(0xffffffffu, s, 2, 4);
            q += __shfl_xor_sync(0xffffffffu, q, 2, 4);
            float mu  = s * (1.f / 64.f);
            float var = q * (1.f / 64.f) - mu * mu;
            float inv = rsqrtf(var + LN_EPS);

            float* dst = g_h + (base + row) * CMID + 2 * ql;   // padded
#pragma unroll
            for (int nt = 0; nt < 8; nt++) {
                float2 o;
                o.x = tf32r(fmaxf((d[mt][nt][2 * h]     - mu) * inv * lg[nt].x + lb[nt].x, 0.f));
                o.y = tf32r(fmaxf((d[mt][nt][2 * h + 1] - mu) * inv * lg[nt].y + lb[nt].y, 0.f));
                *(float2*)(dst + nt * 8) = o;
            }
        }
    }
}

// ---------------------------------------------------------------------------
// Kernel B (tensor): h2 = relu(LN(sum_k gather(h)[k] @ W2[k])), tf32-rounded out.
// Tile 256 rows, 27 k-steps, cp.async double buffer.
// ---------------------------------------------------------------------------
__global__ void __launch_bounds__(256, 1) kB(const int*   __restrict__ nidx,
                                             const float* __restrict__ g2v,
                                             const float* __restrict__ b2v)
{
    extern __shared__ float sm[];
    float* As = sm;                  // 2 x [256][68]
    float* Bf = sm + 2 * KB_AS;      // 2 x [4096]

    const int t    = threadIdx.x;
    const int base = blockIdx.x * 256;
    const int lane = t & 31, w = t >> 5;
    const int qr = lane >> 2, ql = lane & 3;

    const unsigned As_s = (unsigned)__cvta_generic_to_shared(As);
    const unsigned Bf_s = (unsigned)__cvta_generic_to_shared(Bf);

    auto prefetch = [&](int k, int buf) {
        const float4* bsrc = (const float4*)(g_W2f + k * 2048);
        unsigned bb = Bf_s + buf * (KB_BS * 4);
#pragma unroll
        for (int i = 0; i < 4; i++) {
            int u = t + 256 * i;
            cp16(bb + u * 16, bsrc + u);
        }
        unsigned ab = As_s + buf * (KB_AS * 4);
#pragma unroll
        for (int i = 0; i < 16; i++) {
            int u = t + 256 * i;
            int r = u >> 4, c4 = u & 15;
            int gr = base + r;
            int src = (gr < N_PTS) ? __ldg(nidx + gr * KNB + k) : 0;
            cp16(ab + (r * 68 + c4 * 4) * 4, g_h + src * CMID + c4 * 4);
        }
        cp_commit();
    };

    float d[2][8][4];
#pragma unroll
    for (int mt = 0; mt < 2; mt++)
#pragma unroll
        for (int nt = 0; nt < 8; nt++)
#pragma unroll
            for (int p = 0; p < 4; p++) d[mt][nt][p] = 0.f;

    prefetch(0, 0);
    for (int k = 0; k < KNB; k++) {
        const int buf = k & 1;
        if (k < KNB - 1) { prefetch(k + 1, buf ^ 1); cp_wait1(); } else cp_wait0();
        __syncthreads();

        const unsigned* Ab = (const unsigned*)(As + buf * KB_AS);
        const float2*   Bb = (const float2*)(Bf + buf * KB_BS);

#pragma unroll
        for (int kc = 0; kc < 8; kc++) {
            unsigned a[2][4];
#pragma unroll
            for (int mt = 0; mt < 2; mt++) {
                int r0 = w * 32 + mt * 16 + qr;
                int c0 = kc * 8 + ql;
                a[mt][0] = Ab[r0 * 68 + c0];
                a[mt][1] = Ab[(r0 + 8) * 68 + c0];
                a[mt][2] = Ab[r0 * 68 + c0 + 4];
                a[mt][3] = Ab[(r0 + 8) * 68 + c0 + 4];
            }
            unsigned b[8][2];
#pragma unroll
            for (int nt = 0; nt < 8; nt++) {
                float2 bv = Bb[(kc * 8 + nt) * 32 + lane];
                b[nt][0] = __float_as_uint(bv.x);
                b[nt][1] = __float_as_uint(bv.y);
            }
#pragma unroll
            for (int mt = 0; mt < 2; mt++)
#pragma unroll
                for (int nt = 0; nt < 8; nt++)
                    mma_tf32(d[mt][nt], a[mt], b[nt]);
        }
        __syncthreads();
    }

    float2 lg[8], lb[8];
#pragma unroll
    for (int nt = 0; nt < 8; nt++) {
        lg[nt] = __ldg((const float2*)(g2v + nt * 8 + 2 * ql));
        lb[nt] = __ldg((const float2*)(b2v + nt * 8 + 2 * ql));
    }

#pragma unroll
    for (int mt = 0; mt < 2; mt++) {
#pragma unroll
        for (int h = 0; h < 2; h++) {
            int row = w * 32 + mt * 16 + qr + 8 * h;
            float s = 0.f, q = 0.f;
#pragma unroll
            for (int nt = 0; nt < 8; nt++) {
                float v0 = d[mt][nt][2 * h], v1 = d[mt][nt][2 * h + 1];
                s += v0 + v1; q += v0 * v0 + v1 * v1;
            }
            s += __shfl_xor_sync(0xffffffffu, s, 1, 4);
            q += __shfl_xor_sync(0xffffffffu, q, 1, 4);
            s += __shfl_xor_sync(0xffffffffu, s, 2, 4);
            q += __shfl_xor_sync(0xffffffffu, q, 2, 4);
            float mu  = s * (1.f / 64.f);
            float var = q * (1.f / 64.f) - mu * mu;
            float inv = rsqrtf(var + LN_EPS);

            float* dst = g_h2 + (base + row) * CMID + 2 * ql;   // padded
#pragma unroll
            for (int nt = 0; nt < 8; nt++) {
                float2 o;
                o.x = tf32r(fmaxf((d[mt][nt][2 * h]     - mu) * inv * lg[nt].x + lb[nt].x, 0.f));
                o.y = tf32r(fmaxf((d[mt][nt][2 * h + 1] - mu) * inv * lg[nt].y + lb[nt].y, 0.f));
                *(float2*)(dst + nt * 8) = o;
            }
        }
    }
}

// ---------------------------------------------------------------------------
// Kernel C (tensor): out = relu(LN(h2 @ W3) + feats)
// Tile 64 rows x 256 cols, K=64. 8 warps: wr=w>>2 (2x32 rows), wc=w&3 (4x64 cols).
// A = h2 (already tf32), B = W3 frags staged once (64KB).
// ---------------------------------------------------------------------------
__global__ void __launch_bounds__(256, 1) kC(const float* __restrict__ feats,
                                             const float* __restrict__ g3v,
                                             const float* __restrict__ b3v,
                                             float* __restrict__ out)
{
    extern __shared__ float sm[];
    float* hs = sm;                 // [64][68]
    float* Bs = sm + 64 * 68;       // [16384] = W3 frags (float2 x 8192, 64KB)

    const int t    = threadIdx.x;
    const int base = blockIdx.x * 64;
    const int lane = t & 31, w = t >> 5;
    const int wr = w >> 2, wc = w & 3;
    const int qr = lane >> 2, ql = lane & 3;

    // Stage A (g_h2 padded, no guard)
#pragma unroll
    for (int i = 0; i < 4; i++) {
        int u = t + 256 * i;
        int r = u >> 4, c4 = u & 15;
        float4 v = *(const float4*)(g_h2 + (base + r) * CMID + c4 * 4);
        *(float4*)&hs[r * 68 + c4 * 4] = v;
    }
    // Stage B frags (4096 float4 = 64KB)
#pragma unroll
    for (int i = 0; i < 16; i++) {
        int u = t + 256 * i;
        *(float4*)&Bs[u * 4] = __ldg((const float4*)g_W3f + u);
    }
    __syncthreads();

    float d[2][8][4];
#pragma unroll
    for (int mt = 0; mt < 2; mt++)
#pragma unroll
        for (int nt = 0; nt < 8; nt++)
#pragma unroll
            for (int p = 0; p < 4; p++) d[mt][nt][p] = 0.f;

    const unsigned* Ab = (const unsigned*)hs;
    const float2*   Bb = (const float2*)Bs;

#pragma unroll
    for (int kc = 0; kc < 8; kc++) {
        unsigned a[2][4];
#pragma unroll
        for (int mt = 0; mt < 2; mt++) {
            int r0 = wr * 32 + mt * 16 + qr;
            int c0 = kc * 8 + ql;
            a[mt][0] = Ab[r0 * 68 + c0];
            a[mt][1] = Ab[(r0 + 8) * 68 + c0];
            a[mt][2] = Ab[r0 * 68 + c0 + 4];
            a[mt][3] = Ab[(r0 + 8) * 68 + c0 + 4];
        }
        unsigned b[8][2];
#pragma unroll
        for (int nt = 0; nt < 8; nt++) {
            float2 bv = Bb[(kc * 32 + wc * 8 + nt) * 32 + lane];
            b[nt][0] = __float_as_uint(bv.x);
            b[nt][1] = __float_as_uint(bv.y);
        }
#pragma unroll
        for (int mt = 0; mt < 2; mt++)
#pragma unroll
            for (int nt = 0; nt < 8; nt++)
                mma_tf32(d[mt][nt], a[mt], b[nt]);
    }

    // LN over 256 cols: quad partials -> smem [64][4] -> combine
    __syncthreads();
    float2* red = (float2*)hs;      // reuse (64*4 float2 = 2KB)
#pragma unroll
    for (int mt = 0; mt < 2; mt++) {
#pragma unroll
        for (int h = 0; h < 2; h++) {
            int row = wr * 32 + mt * 16 + qr + 8 * h;
            float s = 0.f, q = 0.f;
#pragma unroll
            for (int nt = 0; nt < 8; nt++) {
                float v0 = d[mt][nt][2 * h], v1 = d[mt][nt][2 * h + 1];
                s += v0 + v1; q += v0 * v0 + v1 * v1;
            }
            s += __shfl_xor_sync(0xffffffffu, s, 1, 4);
            q += __shfl_xor_sync(0xffffffffu, q, 1, 4);
            s += __shfl_xor_sync(0xffffffffu, s, 2, 4);
            q += __shfl_xor_sync(0xffffffffu, q, 2, 4);
            if (ql == 0) red[row * 4 + wc] = make_float2(s, q);
        }
    }
    __syncthreads();

    float2 lg[8], lb[8];
#pragma unroll
    for (int nt = 0; nt < 8; nt++) {
        lg[nt] = __ldg((const float2*)(g3v + wc * 64 + nt * 8 + 2 * ql));
        lb[nt] = __ldg((const float2*)(b3v + wc * 64 + nt * 8 + 2 * ql));
    }

#pragma unroll
    for (int mt = 0; mt < 2; mt++) {
#pragma unroll
        for (int h = 0; h < 2; h++) {
            int row  = wr * 32 + mt * 16 + qr + 8 * h;
            int grow = base + row;
            float2 p0 = red[row * 4 + 0], p1 = red[row * 4 + 1];
            float2 p2 = red[row * 4 + 2], p3 = red[row * 4 + 3];
            float S = p0.x + p1.x + p2.x + p3.x;
            float Q = p0.y + p1.y + p2.y + p3.y;
            float mu  = S * (1.f / 256.f);
            float var = Q * (1.f / 256.f) - mu * mu;
            float inv = rsqrtf(var + LN_EPS);

            if (grow < N_PTS) {
                const float* fsrc = feats + grow * CIN + wc * 64 + 2 * ql;
                float* dst = out + grow * COUT + wc * 64 + 2 * ql;
#pragma unroll
                for (int nt = 0; nt < 8; nt++) {
                    float2 r4 = __ldg((const float2*)(fsrc + nt * 8));
                    float2 o;
                    o.x = fmaxf((d[mt][nt][2 * h]     - mu) * inv * lg[nt].x + lb[nt].x + r4.x, 0.f);
                    o.y = fmaxf((d[mt][nt][2 * h + 1] - mu) * inv * lg[nt].y + lb[nt].y + r4.y, 0.f);
                    *(float2*)(dst + nt * 8) = o;
                }
            }
        }
    }
}

// ---------------------------------------------------------------------------
extern "C" void kernel_launch(void* const* d_in, const int* in_sizes, int n_in,
                              void* d_out, int out_size)
{
    const float* feats = (const float*)d_in[0];
    const int*   nidx  = (const int*)  d_in[1];
    const float* W1    = (const float*)d_in[2];
    const float* g1    = (const float*)d_in[3];
    const float* b1    = (const float*)d_in[4];
    const float* W2    = (const float*)d_in[5];
    const float* g2    = (const float*)d_in[6];
    const float* b2    = (const float*)d_in[7];
    const float* W3    = (const float*)d_in[8];
    const float* g3    = (const float*)d_in[9];
    const float* b3    = (const float*)d_in[10];
    float* out = (float*)d_out;

    cudaFuncSetAttribute(kA, cudaFuncAttributeMaxDynamicSharedMemorySize, SMEM_AB);
    cudaFuncSetAttribute(kB, cudaFuncAttributeMaxDynamicSharedMemorySize, SMEM_AB);
    cudaFuncSetAttribute(kC, cudaFuncAttributeMaxDynamicSharedMemorySize, SMEM_C);

    kPrep<<<KNB + 2, 256>>>(W1, W2, W3);
    kA<<<N_PAD / 256, 256, SMEM_AB>>>(feats, g1, b1);
    kB<<<N_PAD / 256, 256, SMEM_AB>>>(nidx, g2, b2);
    kC<<<N_PAD / 64, 256, SMEM_C>>>(feats, g3, b3, out);
}